// round 13
// baseline (speedup 1.0000x reference)
#include <cuda_runtime.h>
#include <cuda_fp16.h>
#include <cstdint>
#include <cstring>
#include <math.h>

#define NN 50000
#define EE 600000
#define HH 128
#define SP 132          // pk kernel padded stride (floats)
#define NPT 782         // ceil(NN/64) node tiles
#define NT 4688         // ceil(EE/128) edge tiles
#define GRID 148

// ---- fused kernel smem byte offsets ----
#define OFF_WG    0          // 128*136 half = 34816
#define OFF_WR    34816
#define OFF_H     69632      // h16 tile, 128 rows * 136 halves
#define OFF_E     104448     // ea16 tile
#define OFF_EA32  139264     // edge_attr fp32 tile, 128*128*4 = 65536
#define OFF_IDX   204800     // 256 ints = 1024
#define OFF_WC    205824     // 10*128 floats = 5120
#define FSMEM     210944

// Scratch (__device__ globals: alloc-free rule)
__device__ __align__(16) float g_Pi[NN * HH];
__device__ __align__(16) float g_Pj[NN * HH];
__device__ __align__(16) float g_Wcomb[10 * HH];

__device__ __forceinline__ float sigmoidf_(float x) {
    return 1.0f / (1.0f + __expf(-x));
}
__device__ __forceinline__ uint32_t h2u(__half2 v) {
    uint32_t r;
    memcpy(&r, &v, 4);
    return r;
}
__device__ __forceinline__ unsigned f2tf32(float x) {
    unsigned r;
    asm("cvt.rna.tf32.f32 %0, %1;" : "=r"(r) : "f"(x));
    return r;
}
__device__ __forceinline__ uint32_t smem_u32(const void* smem_ptr) {
    uint32_t addr;
    asm("{ .reg .u64 tmp; cvta.to.shared.u64 tmp, %1; cvt.u32.u64 %0, tmp; }"
        : "=r"(addr) : "l"(smem_ptr));
    return addr;
}
__device__ __forceinline__ void mma_tf32(float* d, unsigned a0, unsigned a1,
                                         unsigned a2, unsigned a3,
                                         unsigned b0, unsigned b1) {
    asm volatile(
        "mma.sync.aligned.m16n8k8.row.col.f32.tf32.tf32.f32 "
        "{%0,%1,%2,%3}, {%4,%5,%6,%7}, {%8,%9}, {%0,%1,%2,%3};\n"
        : "+f"(d[0]), "+f"(d[1]), "+f"(d[2]), "+f"(d[3])
        : "r"(a0), "r"(a1), "r"(a2), "r"(a3), "r"(b0), "r"(b1));
}
__device__ __forceinline__ void mma_f16(float* d, uint32_t a0, uint32_t a1,
                                        uint32_t a2, uint32_t a3,
                                        uint32_t b0, uint32_t b1) {
    asm volatile(
        "mma.sync.aligned.m16n8k16.row.col.f32.f16.f16.f32 "
        "{%0,%1,%2,%3}, {%4,%5,%6,%7}, {%8,%9}, {%0,%1,%2,%3};\n"
        : "+f"(d[0]), "+f"(d[1]), "+f"(d[2]), "+f"(d[3])
        : "r"(a0), "r"(a1), "r"(a2), "r"(a3), "r"(b0), "r"(b1));
}

#define CP_ASYNC_16(dst_u32, src_ptr) \
    asm volatile("cp.async.cg.shared.global [%0], [%1], 16;" \
                 :: "r"(dst_u32), "l"(src_ptr) : "memory")
#define CP_COMMIT() asm volatile("cp.async.commit_group;" ::: "memory")
#define CP_WAIT(n)  asm volatile("cp.async.wait_group %0;" :: "n"(n) : "memory")

// ---------------------------------------------------------------------------
// Setup kernel: wcomb (blocks 0-9) + P precompute (tf32 mma).
// PERSISTENT: 148 CTAs loop over node tiles; weights staged once per CTA.
// ---------------------------------------------------------------------------
__global__ __launch_bounds__(256, 1) void pk_kernel(const float* __restrict__ Ei,
                                                    const float* __restrict__ Ej,
                                                    const float* __restrict__ Wsem,
                                                    const float* __restrict__ Wgeo,
                                                    const float* __restrict__ Wpair) {
    extern __shared__ float sm[];
    float* sWt = sm;
    float* sWb = sWt + 128 * SP;
    float* sAi = sWb + 128 * SP;
    float* sAj = sAi + 64 * SP;

    int tid = threadIdx.x;
    int lane = tid & 31;
    int w = tid >> 5;

    if (blockIdx.x < 10 && tid < 128) {
        int c = tid;
        int d = blockIdx.x;
        int dd = d % 5;
        const float* wp = Wpair + (d / 5) * 128 * HH;
        float acc = 0.0f;
#pragma unroll 16
        for (int m = 0; m < 128; m++)
            acc = fmaf(Wgeo[dd * HH + m], wp[m * HH + c], acc);
        g_Wcomb[d * HH + c] = acc;
    }

    for (int i = tid; i < 4096; i += 256) {
        int k = i >> 5, c4 = i & 31;
        float4 t = ((const float4*)Wsem)[i];
        float4 b = ((const float4*)(Wsem + 128 * HH))[i];
        *(uint4*)&sWt[k * SP + c4 * 4] =
            make_uint4(f2tf32(t.x), f2tf32(t.y), f2tf32(t.z), f2tf32(t.w));
        *(uint4*)&sWb[k * SP + c4 * 4] =
            make_uint4(f2tf32(b.x), f2tf32(b.y), f2tf32(b.z), f2tf32(b.w));
    }

    const float* A = (w < 4) ? sAi : sAj;
    const float* W = (w < 4) ? sWt : sWb;
    int nb = (w & 3) * 32;
    int gid = lane >> 2, tig = lane & 3;

    for (int t = blockIdx.x; t < NPT; t += (int)gridDim.x) {
        int base = t * 64;
        __syncthreads();
        for (int i = tid; i < 2048; i += 256) {
            int r = i >> 5, c4 = i & 31;
            int row = base + r;
            float4 v = make_float4(0.f, 0.f, 0.f, 0.f);
            float4 u = make_float4(0.f, 0.f, 0.f, 0.f);
            if (row < NN) {
                v = ((const float4*)Ei)[row * 32 + c4];
                u = ((const float4*)Ej)[row * 32 + c4];
            }
            *(uint4*)&sAi[r * SP + c4 * 4] =
                make_uint4(f2tf32(v.x), f2tf32(v.y), f2tf32(v.z), f2tf32(v.w));
            *(uint4*)&sAj[r * SP + c4 * 4] =
                make_uint4(f2tf32(u.x), f2tf32(u.y), f2tf32(u.z), f2tf32(u.w));
        }
        __syncthreads();

        float acc[4][4][4];
#pragma unroll
        for (int mt = 0; mt < 4; mt++)
#pragma unroll
            for (int nt = 0; nt < 4; nt++)
#pragma unroll
                for (int q = 0; q < 4; q++) { acc[mt][nt][q] = 0.f; }

#pragma unroll
        for (int kt = 0; kt < 16; kt++) {
            int k0 = kt * 8;
            unsigned b[4][2];
#pragma unroll
            for (int nt = 0; nt < 4; nt++) {
                int n = nb + nt * 8 + gid;
                b[nt][0] = __float_as_uint(W[(k0 + tig) * SP + n]);
                b[nt][1] = __float_as_uint(W[(k0 + 4 + tig) * SP + n]);
            }
#pragma unroll
            for (int mt = 0; mt < 4; mt++) {
                int m = mt * 16;
                unsigned a0 = __float_as_uint(A[(m + gid) * SP + k0 + tig]);
                unsigned a1 = __float_as_uint(A[(m + gid + 8) * SP + k0 + tig]);
                unsigned a2 = __float_as_uint(A[(m + gid) * SP + k0 + tig + 4]);
                unsigned a3 = __float_as_uint(A[(m + gid + 8) * SP + k0 + tig + 4]);
#pragma unroll
                for (int nt = 0; nt < 4; nt++)
                    mma_tf32(acc[mt][nt], a0, a1, a2, a3, b[nt][0], b[nt][1]);
            }
        }

        float* G = (w < 4) ? g_Pi : g_Pj;
#pragma unroll
        for (int mt = 0; mt < 4; mt++)
#pragma unroll
            for (int nt = 0; nt < 4; nt++) {
                int row0 = base + mt * 16 + gid;
                int col = nb + nt * 8 + 2 * tig;
                if (row0 < NN)
                    *(float2*)&G[(size_t)row0 * HH + col] =
                        make_float2(acc[mt][nt][0], acc[mt][nt][1]);
                int row1 = row0 + 8;
                if (row1 < NN)
                    *(float2*)&G[(size_t)row1 * HH + col] =
                        make_float2(acc[mt][nt][2], acc[mt][nt][3]);
            }
    }
}

// ---------------------------------------------------------------------------
// FUSED kernel: phaseA + GEMM + epilogue, persistent 148 CTAs x 512 threads.
// Per 128-edge tile: phase A -> h16/ea16 smem tiles -> fp16 mma -> out.
// edge_attr + eidx for the NEXT tile prefetched via cp.async during GEMM.
// ---------------------------------------------------------------------------
__global__ __launch_bounds__(512, 1) void fused_kernel(
    const float* __restrict__ pos_i, const float* __restrict__ pos_j,
    const float* __restrict__ hd_i, const float* __restrict__ hd_j,
    const int* __restrict__ eidx, const float* __restrict__ edge_attr,
    const float* __restrict__ b_sem, const float* __restrict__ gamma,
    const float* __restrict__ beta, const float* __restrict__ Wgate,
    const float* __restrict__ Wres, float* __restrict__ out) {
    extern __shared__ char smc[];
    __half* sWg = (__half*)(smc + OFF_WG);
    __half* sWr = (__half*)(smc + OFF_WR);
    __half* sH  = (__half*)(smc + OFF_H);
    __half* sE  = (__half*)(smc + OFF_E);
    float*  sEA = (float*)(smc + OFF_EA32);
    int*    sIdx = (int*)(smc + OFF_IDX);
    float*  sWc = (float*)(smc + OFF_WC);
    uint32_t sb = smem_u32(smc);

    int tid = threadIdx.x;
    int lane = tid & 31;
    int w = tid >> 5;
    int col = lane * 4;
    int gid = lane >> 2;
    int tig = lane & 3;
    int mb = (w >> 2) * 32;
    int nb = (w & 3) * 32;

    // stage weights (transposed, stride 136) + wcomb table
    for (int i = tid; i < 16384; i += 512) {
        int n = i & 127, k = i >> 7;
        sWg[n * 136 + k] = __float2half(Wgate[k * HH + n]);
        sWr[n * 136 + k] = __float2half(Wres[k * HH + n]);
    }
    for (int i = tid; i < 1280; i += 512) sWc[i] = g_Wcomb[i];

    float4 bs = *(const float4*)&b_sem[col];
    float4 gm = *(const float4*)&gamma[col];
    float4 bt = *(const float4*)&beta[col];

    // prologue: prefetch first tile's eidx + edge_attr
    {
        long nbase = (long)blockIdx.x * 128;
        if (tid < 64) {
            long off = nbase + (tid & 31) * 4;
            if (off > EE - 4) off = EE - 4;
            const int* srcp = (tid < 32) ? (eidx + off) : (eidx + EE + off);
            CP_ASYNC_16(sb + OFF_IDX + ((tid < 32) ? 0 : 512) + (tid & 31) * 16, srcp);
        }
        for (int c = tid; c < 4096; c += 512) {
            int row = c >> 5, q = c & 31;
            long e = nbase + row;
            if (e >= EE) e = EE - 1;
            CP_ASYNC_16(sb + OFF_EA32 + row * 512 + q * 16, edge_attr + e * HH + q * 4);
        }
        CP_COMMIT();
    }
    CP_WAIT(0);
    __syncthreads();

    for (int t = blockIdx.x; t < NT; t += GRID) {
        long base = (long)t * 128;

        // ---- Phase A: 16 warps x 8 edges -> sH / sE ----
#pragma unroll 2
        for (int it = 0; it < 8; it++) {
            int row = w + 16 * it;
            int src = sIdx[row];
            int tgt = sIdx[128 + row];

            float2 pvi = __ldg(&((const float2*)pos_i)[src]);
            float2 pvj = __ldg(&((const float2*)pos_j)[tgt]);
            float ang_i = __ldg(&hd_i[src]);
            float ang_j = __ldg(&hd_j[tgt]);
            float dx = pvi.x - pvj.x;
            float dy = pvi.y - pvj.y;

            float sj, cj;
            __sincosf(ang_j, &sj, &cj);
            float x1 = dx * cj + dy * sj;
            float y1 = -dx * sj + dy * cj;
            float len1 = sqrtf(x1 * x1 + y1 * y1);
            float il1 = (len1 > 0.f) ? (1.f / len1) : 0.f;
            float ct1 = (len1 > 0.f) ? (x1 * il1) : 1.f;
            float st1 = y1 * il1;

            float si, ci;
            __sincosf(ang_i, &si, &ci);
            float x2 = -dx * ci - dy * si;
            float y2 = dx * si - dy * ci;
            float len2 = sqrtf(x2 * x2 + y2 * y2);
            float il2 = (len2 > 0.f) ? (1.f / len2) : 0.f;
            float ct2 = (len2 > 0.f) ? (x2 * il2) : 1.f;
            float st2 = y2 * il2;

            float shd, chd;
            __sincosf(ang_i - ang_j, &shd, &chd);

            float raw[10];
            raw[0] = len1; raw[1] = ct1; raw[2] = st1; raw[3] = chd; raw[4] = shd;
            raw[5] = len2; raw[6] = ct2; raw[7] = st2; raw[8] = chd; raw[9] = -shd;

            float4 g = make_float4(0.f, 0.f, 0.f, 0.f);
#pragma unroll
            for (int d = 0; d < 10; d++) {
                float4 wc = *(const float4*)&sWc[d * HH + col];
                g.x = fmaf(raw[d], wc.x, g.x);
                g.y = fmaf(raw[d], wc.y, g.y);
                g.z = fmaf(raw[d], wc.z, g.z);
                g.w = fmaf(raw[d], wc.w, g.w);
            }
            g.x = fmaxf(g.x, 0.f); g.y = fmaxf(g.y, 0.f);
            g.z = fmaxf(g.z, 0.f); g.w = fmaxf(g.w, 0.f);

            float4 Pi4 = __ldg((const float4*)&g_Pi[(size_t)src * HH + col]);
            float4 Pj4 = __ldg((const float4*)&g_Pj[(size_t)tgt * HH + col]);
            float4 ea4 = *(const float4*)&sEA[row * HH + col];

            float4 pre;
            pre.x = fmaf(g.x, sigmoidf_(Pi4.x + Pj4.x + bs.x), ea4.x);
            pre.y = fmaf(g.y, sigmoidf_(Pi4.y + Pj4.y + bs.y), ea4.y);
            pre.z = fmaf(g.z, sigmoidf_(Pi4.z + Pj4.z + bs.z), ea4.z);
            pre.w = fmaf(g.w, sigmoidf_(Pi4.w + Pj4.w + bs.w), ea4.w);

            float ssum = pre.x + pre.y + pre.z + pre.w;
#pragma unroll
            for (int off = 16; off >= 1; off >>= 1)
                ssum += __shfl_xor_sync(0xffffffffu, ssum, off);
            float mu = ssum * (1.0f / 128.0f);
            float4 dv;
            dv.x = pre.x - mu; dv.y = pre.y - mu;
            dv.z = pre.z - mu; dv.w = pre.w - mu;
            float sq = dv.x * dv.x + dv.y * dv.y + dv.z * dv.z + dv.w * dv.w;
#pragma unroll
            for (int off = 16; off >= 1; off >>= 1)
                sq += __shfl_xor_sync(0xffffffffu, sq, off);
            float rstd = rsqrtf(sq * (1.0f / 128.0f) + 1e-5f);

            float4 h4;
            h4.x = fmaf(dv.x * rstd, gm.x, bt.x);
            h4.y = fmaf(dv.y * rstd, gm.y, bt.y);
            h4.z = fmaf(dv.z * rstd, gm.z, bt.z);
            h4.w = fmaf(dv.w * rstd, gm.w, bt.w);

            __half2 hh0 = __float22half2_rn(make_float2(h4.x, h4.y));
            __half2 hh1 = __float22half2_rn(make_float2(h4.z, h4.w));
            *(uint2*)&sH[row * 136 + col] = make_uint2(h2u(hh0), h2u(hh1));

            __half2 ee0 = __float22half2_rn(make_float2(ea4.x, ea4.y));
            __half2 ee1 = __float22half2_rn(make_float2(ea4.z, ea4.w));
            *(uint2*)&sE[row * 136 + col] = make_uint2(h2u(ee0), h2u(ee1));
        }
        __syncthreads();   // phase A done: sH/sE valid, sEA/sIdx consumable

        // ---- prefetch NEXT tile's eidx + edge_attr (overlaps GEMM) ----
        int nt2 = t + GRID;
        if (nt2 < NT) {
            long nbase = (long)nt2 * 128;
            if (tid < 64) {
                long off = nbase + (tid & 31) * 4;
                if (off > EE - 4) off = EE - 4;
                const int* srcp = (tid < 32) ? (eidx + off) : (eidx + EE + off);
                CP_ASYNC_16(sb + OFF_IDX + ((tid < 32) ? 0 : 512) + (tid & 31) * 16, srcp);
            }
            for (int c = tid; c < 4096; c += 512) {
                int row = c >> 5, q = c & 31;
                long e = nbase + row;
                if (e >= EE) e = EE - 1;
                CP_ASYNC_16(sb + OFF_EA32 + row * 512 + q * 16,
                            edge_attr + e * HH + q * 4);
            }
            CP_COMMIT();
        }

        // ---- GEMM: gate = h @ Wg, res = ea @ Wr ----
        float aG[2][4][4];
        float aR[2][4][4];
#pragma unroll
        for (int mt = 0; mt < 2; mt++)
#pragma unroll
            for (int nt = 0; nt < 4; nt++)
#pragma unroll
                for (int q = 0; q < 4; q++) { aG[mt][nt][q] = 0.f; aR[mt][nt][q] = 0.f; }

#pragma unroll
        for (int kt = 0; kt < 8; kt++) {
            int k0 = kt * 16;
            uint32_t bg[4][2], br[4][2];
#pragma unroll
            for (int nt = 0; nt < 4; nt++) {
                int n = nb + nt * 8 + gid;
                bg[nt][0] = *(const uint32_t*)&sWg[n * 136 + k0 + 2 * tig];
                bg[nt][1] = *(const uint32_t*)&sWg[n * 136 + k0 + 2 * tig + 8];
                br[nt][0] = *(const uint32_t*)&sWr[n * 136 + k0 + 2 * tig];
                br[nt][1] = *(const uint32_t*)&sWr[n * 136 + k0 + 2 * tig + 8];
            }
#pragma unroll
            for (int mt = 0; mt < 2; mt++) {
                int r0 = mb + mt * 16 + gid;
                uint32_t ha0 = *(const uint32_t*)&sH[r0 * 136 + k0 + 2 * tig];
                uint32_t ha1 = *(const uint32_t*)&sH[(r0 + 8) * 136 + k0 + 2 * tig];
                uint32_t ha2 = *(const uint32_t*)&sH[r0 * 136 + k0 + 2 * tig + 8];
                uint32_t ha3 = *(const uint32_t*)&sH[(r0 + 8) * 136 + k0 + 2 * tig + 8];
                uint32_t ea0 = *(const uint32_t*)&sE[r0 * 136 + k0 + 2 * tig];
                uint32_t ea1 = *(const uint32_t*)&sE[(r0 + 8) * 136 + k0 + 2 * tig];
                uint32_t ea2 = *(const uint32_t*)&sE[r0 * 136 + k0 + 2 * tig + 8];
                uint32_t ea3 = *(const uint32_t*)&sE[(r0 + 8) * 136 + k0 + 2 * tig + 8];
#pragma unroll
                for (int nt = 0; nt < 4; nt++) {
                    mma_f16(aG[mt][nt], ha0, ha1, ha2, ha3, bg[nt][0], bg[nt][1]);
                    mma_f16(aR[mt][nt], ea0, ea1, ea2, ea3, br[nt][0], br[nt][1]);
                }
            }
        }

        // ---- epilogue: out = h + sigmoid(gate) * (res - h) ----
#pragma unroll
        for (int mt = 0; mt < 2; mt++) {
#pragma unroll
            for (int nt = 0; nt < 4; nt++) {
                int c0 = nb + nt * 8 + 2 * tig;
#pragma unroll
                for (int hf = 0; hf < 2; hf++) {
                    int r = mb + mt * 16 + gid + hf * 8;
                    long e = base + r;
                    if (e < EE) {
                        float2 h2 = __half22float2(*(const __half2*)&sH[r * 136 + c0]);
                        float s0 = sigmoidf_(aG[mt][nt][hf * 2 + 0]);
                        float s1 = sigmoidf_(aG[mt][nt][hf * 2 + 1]);
                        float2 o;
                        o.x = fmaf(s0, aR[mt][nt][hf * 2 + 0] - h2.x, h2.x);
                        o.y = fmaf(s1, aR[mt][nt][hf * 2 + 1] - h2.y, h2.y);
                        *(float2*)&out[(size_t)e * HH + c0] = o;
                    }
                }
            }
        }
        CP_WAIT(0);
        __syncthreads();   // next tile's sEA/sIdx ready; sH/sE free for reuse
    }
}

// ---------------------------------------------------------------------------
extern "C" void kernel_launch(void* const* d_in, const int* in_sizes, int n_in,
                              void* d_out, int out_size) {
    const float* pos_i     = (const float*)d_in[0];
    const float* pos_j     = (const float*)d_in[1];
    const float* hd_i      = (const float*)d_in[2];
    const float* hd_j      = (const float*)d_in[3];
    const int*   eidx      = (const int*)d_in[4];
    const float* edge_attr = (const float*)d_in[5];
    const float* embs_i    = (const float*)d_in[6];
    const float* embs_j    = (const float*)d_in[7];
    const float* Wgeo      = (const float*)d_in[8];
    const float* Wpair     = (const float*)d_in[9];
    const float* Wsem      = (const float*)d_in[10];
    const float* bsem      = (const float*)d_in[11];
    const float* gamma     = (const float*)d_in[12];
    const float* beta      = (const float*)d_in[13];
    const float* Wgate     = (const float*)d_in[14];
    const float* Wres      = (const float*)d_in[15];

    const int smem_pk = (128 * SP * 2 + 64 * SP * 2) * 4;  // 202752

    cudaFuncSetAttribute(pk_kernel, cudaFuncAttributeMaxDynamicSharedMemorySize,
                         smem_pk);
    cudaFuncSetAttribute(fused_kernel, cudaFuncAttributeMaxDynamicSharedMemorySize,
                         FSMEM);

    pk_kernel<<<148, 256, smem_pk>>>(embs_i, embs_j, Wsem, Wgeo, Wpair);
    fused_kernel<<<GRID, 512, FSMEM>>>(pos_i, pos_j, hd_i, hd_j, eidx, edge_attr,
                                       bsem, gamma, beta, Wgate, Wres,
                                       (float*)d_out);
}

// round 14
// speedup vs baseline: 1.2278x; 1.2278x over previous
#include <cuda_runtime.h>
#include <cuda_fp16.h>
#include <cstdint>
#include <cstring>
#include <math.h>

#define NN 50000
#define EE 600000
#define HH 128
#define SP 132          // pk kernel padded stride (floats)
#define NPT 782         // ceil(NN/64) node tiles
#define NT2 9375        // EE/64 tiles (phaseA + gemm)
#define PGRID 296
#define GGRID 296

// ---- phaseA smem byte offsets (dynamic) ----
#define AOFF_WC   0          // 10*128 floats = 5120
#define AOFF_IDX0 5120       // 64 src + 64 tgt ints = 512
#define AOFF_IDX1 5632
#define AOFF_EA0  6144       // 64*128 floats = 32768
#define AOFF_EA1  38912
#define ASMEM     71680

// ---- gemm smem byte offsets (dynamic) ----
#define GOFF_WG   0          // 128*136 half = 34816
#define GOFF_WR   34816
#define GOFF_H    69632      // 64*136 half = 17408
#define GOFF_E    87040
#define GSMEM     104448

// Scratch (__device__ globals: alloc-free rule)
__device__ __align__(16) float  g_Pi[NN * HH];
__device__ __align__(16) float  g_Pj[NN * HH];
__device__ __align__(16) float  g_Wcomb[10 * HH];
__device__ __align__(16) __half g_H16[(size_t)EE * HH];
__device__ __align__(16) __half g_EA16[(size_t)EE * HH];

__device__ __forceinline__ float sigmoidf_(float x) {
    return 1.0f / (1.0f + __expf(-x));
}
__device__ __forceinline__ uint32_t h2u(__half2 v) {
    uint32_t r;
    memcpy(&r, &v, 4);
    return r;
}
__device__ __forceinline__ unsigned f2tf32(float x) {
    unsigned r;
    asm("cvt.rna.tf32.f32 %0, %1;" : "=r"(r) : "f"(x));
    return r;
}
__device__ __forceinline__ uint32_t smem_u32(const void* smem_ptr) {
    uint32_t addr;
    asm("{ .reg .u64 tmp; cvta.to.shared.u64 tmp, %1; cvt.u32.u64 %0, tmp; }"
        : "=r"(addr) : "l"(smem_ptr));
    return addr;
}
__device__ __forceinline__ void mma_tf32(float* d, unsigned a0, unsigned a1,
                                         unsigned a2, unsigned a3,
                                         unsigned b0, unsigned b1) {
    asm volatile(
        "mma.sync.aligned.m16n8k8.row.col.f32.tf32.tf32.f32 "
        "{%0,%1,%2,%3}, {%4,%5,%6,%7}, {%8,%9}, {%0,%1,%2,%3};\n"
        : "+f"(d[0]), "+f"(d[1]), "+f"(d[2]), "+f"(d[3])
        : "r"(a0), "r"(a1), "r"(a2), "r"(a3), "r"(b0), "r"(b1));
}
__device__ __forceinline__ void mma_f16(float* d, uint32_t a0, uint32_t a1,
                                        uint32_t a2, uint32_t a3,
                                        uint32_t b0, uint32_t b1) {
    asm volatile(
        "mma.sync.aligned.m16n8k16.row.col.f32.f16.f16.f32 "
        "{%0,%1,%2,%3}, {%4,%5,%6,%7}, {%8,%9}, {%0,%1,%2,%3};\n"
        : "+f"(d[0]), "+f"(d[1]), "+f"(d[2]), "+f"(d[3])
        : "r"(a0), "r"(a1), "r"(a2), "r"(a3), "r"(b0), "r"(b1));
}

#define CP_ASYNC_16(dst_u32, src_ptr) \
    asm volatile("cp.async.cg.shared.global [%0], [%1], 16;" \
                 :: "r"(dst_u32), "l"(src_ptr) : "memory")
#define CP_COMMIT() asm volatile("cp.async.commit_group;" ::: "memory")
#define CP_WAIT(n)  asm volatile("cp.async.wait_group %0;" :: "n"(n) : "memory")

// ---------------------------------------------------------------------------
// Setup kernel: wcomb (blocks 0-9) + P precompute (tf32 mma).
// PERSISTENT: 148 CTAs loop over node tiles; weights staged once per CTA.
// ---------------------------------------------------------------------------
__global__ __launch_bounds__(256, 1) void pk_kernel(const float* __restrict__ Ei,
                                                    const float* __restrict__ Ej,
                                                    const float* __restrict__ Wsem,
                                                    const float* __restrict__ Wgeo,
                                                    const float* __restrict__ Wpair) {
    extern __shared__ float sm[];
    float* sWt = sm;
    float* sWb = sWt + 128 * SP;
    float* sAi = sWb + 128 * SP;
    float* sAj = sAi + 64 * SP;

    int tid = threadIdx.x;
    int lane = tid & 31;
    int w = tid >> 5;

    if (blockIdx.x < 10 && tid < 128) {
        int c = tid;
        int d = blockIdx.x;
        int dd = d % 5;
        const float* wp = Wpair + (d / 5) * 128 * HH;
        float acc = 0.0f;
#pragma unroll 16
        for (int m = 0; m < 128; m++)
            acc = fmaf(Wgeo[dd * HH + m], wp[m * HH + c], acc);
        g_Wcomb[d * HH + c] = acc;
    }

    for (int i = tid; i < 4096; i += 256) {
        int k = i >> 5, c4 = i & 31;
        float4 t = ((const float4*)Wsem)[i];
        float4 b = ((const float4*)(Wsem + 128 * HH))[i];
        *(uint4*)&sWt[k * SP + c4 * 4] =
            make_uint4(f2tf32(t.x), f2tf32(t.y), f2tf32(t.z), f2tf32(t.w));
        *(uint4*)&sWb[k * SP + c4 * 4] =
            make_uint4(f2tf32(b.x), f2tf32(b.y), f2tf32(b.z), f2tf32(b.w));
    }

    const float* A = (w < 4) ? sAi : sAj;
    const float* W = (w < 4) ? sWt : sWb;
    int nb = (w & 3) * 32;
    int gid = lane >> 2, tig = lane & 3;

    for (int t = blockIdx.x; t < NPT; t += (int)gridDim.x) {
        int base = t * 64;
        __syncthreads();
        for (int i = tid; i < 2048; i += 256) {
            int r = i >> 5, c4 = i & 31;
            int row = base + r;
            float4 v = make_float4(0.f, 0.f, 0.f, 0.f);
            float4 u = make_float4(0.f, 0.f, 0.f, 0.f);
            if (row < NN) {
                v = ((const float4*)Ei)[row * 32 + c4];
                u = ((const float4*)Ej)[row * 32 + c4];
            }
            *(uint4*)&sAi[r * SP + c4 * 4] =
                make_uint4(f2tf32(v.x), f2tf32(v.y), f2tf32(v.z), f2tf32(v.w));
            *(uint4*)&sAj[r * SP + c4 * 4] =
                make_uint4(f2tf32(u.x), f2tf32(u.y), f2tf32(u.z), f2tf32(u.w));
        }
        __syncthreads();

        float acc[4][4][4];
#pragma unroll
        for (int mt = 0; mt < 4; mt++)
#pragma unroll
            for (int nt = 0; nt < 4; nt++)
#pragma unroll
                for (int q = 0; q < 4; q++) { acc[mt][nt][q] = 0.f; }

#pragma unroll
        for (int kt = 0; kt < 16; kt++) {
            int k0 = kt * 8;
            unsigned b[4][2];
#pragma unroll
            for (int nt = 0; nt < 4; nt++) {
                int n = nb + nt * 8 + gid;
                b[nt][0] = __float_as_uint(W[(k0 + tig) * SP + n]);
                b[nt][1] = __float_as_uint(W[(k0 + 4 + tig) * SP + n]);
            }
#pragma unroll
            for (int mt = 0; mt < 4; mt++) {
                int m = mt * 16;
                unsigned a0 = __float_as_uint(A[(m + gid) * SP + k0 + tig]);
                unsigned a1 = __float_as_uint(A[(m + gid + 8) * SP + k0 + tig]);
                unsigned a2 = __float_as_uint(A[(m + gid) * SP + k0 + tig + 4]);
                unsigned a3 = __float_as_uint(A[(m + gid + 8) * SP + k0 + tig + 4]);
#pragma unroll
                for (int nt = 0; nt < 4; nt++)
                    mma_tf32(acc[mt][nt], a0, a1, a2, a3, b[nt][0], b[nt][1]);
            }
        }

        float* G = (w < 4) ? g_Pi : g_Pj;
#pragma unroll
        for (int mt = 0; mt < 4; mt++)
#pragma unroll
            for (int nt = 0; nt < 4; nt++) {
                int row0 = base + mt * 16 + gid;
                int col = nb + nt * 8 + 2 * tig;
                if (row0 < NN)
                    *(float2*)&G[(size_t)row0 * HH + col] =
                        make_float2(acc[mt][nt][0], acc[mt][nt][1]);
                int row1 = row0 + 8;
                if (row1 < NN)
                    *(float2*)&G[(size_t)row1 * HH + col] =
                        make_float2(acc[mt][nt][2], acc[mt][nt][3]);
            }
    }
}

// ---------------------------------------------------------------------------
// Phase A v2: persistent 296 CTAs x 512 thr (occ 2 = 32 warps/SM).
// eidx + edge_attr double-buffered via cp.async one tile ahead.
// Arithmetic identical to R12 (bitwise-same h16/ea16).
// ---------------------------------------------------------------------------
__global__ __launch_bounds__(512, 2) void phaseA_kernel(
    const float* __restrict__ pos_i, const float* __restrict__ pos_j,
    const float* __restrict__ hd_i, const float* __restrict__ hd_j,
    const int* __restrict__ eidx, const float* __restrict__ edge_attr,
    const float* __restrict__ b_sem, const float* __restrict__ gamma,
    const float* __restrict__ beta) {
    extern __shared__ char smc[];
    float* sWc = (float*)(smc + AOFF_WC);
    uint32_t sb = smem_u32(smc);

    int tid = threadIdx.x;
    int lane = tid & 31;
    int w = tid >> 5;
    int col = lane * 4;

    for (int i = tid; i < 1280; i += 512) sWc[i] = g_Wcomb[i];

    float4 bs = *(const float4*)&b_sem[col];
    float4 gm = *(const float4*)&gamma[col];
    float4 bt = *(const float4*)&beta[col];

    const uint32_t idxOff[2] = {AOFF_IDX0, AOFF_IDX1};
    const uint32_t eaOff[2] = {AOFF_EA0, AOFF_EA1};

    // prologue: prefetch first tile into buf 0
    {
        long base = (long)blockIdx.x * 64;
        if (tid < 32) {
            const int* srcp = (tid < 16) ? (eidx + base + (tid & 15) * 4)
                                         : (eidx + EE + base + (tid & 15) * 4);
            CP_ASYNC_16(sb + AOFF_IDX0 + ((tid < 16) ? 0 : 256) + (tid & 15) * 16,
                        srcp);
        }
        for (int c = tid; c < 2048; c += 512) {
            int r = c >> 5, q = c & 31;
            CP_ASYNC_16(sb + AOFF_EA0 + r * 512 + q * 16,
                        edge_attr + (base + r) * HH + q * 4);
        }
        CP_COMMIT();
    }
    CP_WAIT(0);
    __syncthreads();

    int cur = 0;
    for (int t = blockIdx.x; t < NT2; t += PGRID) {
        long base = (long)t * 64;
        const int* sIdx = (const int*)(smc + idxOff[cur]);
        const float* sEA = (const float*)(smc + eaOff[cur]);

        // prefetch NEXT tile into buf^1 (overlaps compute)
        int nt2 = t + PGRID;
        if (nt2 < NT2) {
            long nbase = (long)nt2 * 64;
            if (tid < 32) {
                const int* srcp = (tid < 16) ? (eidx + nbase + (tid & 15) * 4)
                                             : (eidx + EE + nbase + (tid & 15) * 4);
                CP_ASYNC_16(sb + idxOff[cur ^ 1] + ((tid < 16) ? 0 : 256) +
                                (tid & 15) * 16,
                            srcp);
            }
            for (int c = tid; c < 2048; c += 512) {
                int r = c >> 5, q = c & 31;
                CP_ASYNC_16(sb + eaOff[cur ^ 1] + r * 512 + q * 16,
                            edge_attr + (nbase + r) * HH + q * 4);
            }
            CP_COMMIT();
        }

        // compute 64 edges: warp w handles rows w + 16*it
#pragma unroll 2
        for (int it = 0; it < 4; it++) {
            int row = w + 16 * it;
            long e = base + row;
            int src = sIdx[row];
            int tgt = sIdx[64 + row];

            float2 pvi = __ldg(&((const float2*)pos_i)[src]);
            float2 pvj = __ldg(&((const float2*)pos_j)[tgt]);
            float ang_i = __ldg(&hd_i[src]);
            float ang_j = __ldg(&hd_j[tgt]);
            float dx = pvi.x - pvj.x;
            float dy = pvi.y - pvj.y;

            float sj, cj;
            __sincosf(ang_j, &sj, &cj);
            float x1 = dx * cj + dy * sj;
            float y1 = -dx * sj + dy * cj;
            float len1 = sqrtf(x1 * x1 + y1 * y1);
            float il1 = (len1 > 0.f) ? (1.f / len1) : 0.f;
            float ct1 = (len1 > 0.f) ? (x1 * il1) : 1.f;
            float st1 = y1 * il1;

            float si, ci;
            __sincosf(ang_i, &si, &ci);
            float x2 = -dx * ci - dy * si;
            float y2 = dx * si - dy * ci;
            float len2 = sqrtf(x2 * x2 + y2 * y2);
            float il2 = (len2 > 0.f) ? (1.f / len2) : 0.f;
            float ct2 = (len2 > 0.f) ? (x2 * il2) : 1.f;
            float st2 = y2 * il2;

            float shd, chd;
            __sincosf(ang_i - ang_j, &shd, &chd);

            float raw[10];
            raw[0] = len1; raw[1] = ct1; raw[2] = st1; raw[3] = chd; raw[4] = shd;
            raw[5] = len2; raw[6] = ct2; raw[7] = st2; raw[8] = chd; raw[9] = -shd;

            float4 g = make_float4(0.f, 0.f, 0.f, 0.f);
#pragma unroll
            for (int d = 0; d < 10; d++) {
                float4 wc = *(const float4*)&sWc[d * HH + col];
                g.x = fmaf(raw[d], wc.x, g.x);
                g.y = fmaf(raw[d], wc.y, g.y);
                g.z = fmaf(raw[d], wc.z, g.z);
                g.w = fmaf(raw[d], wc.w, g.w);
            }
            g.x = fmaxf(g.x, 0.f); g.y = fmaxf(g.y, 0.f);
            g.z = fmaxf(g.z, 0.f); g.w = fmaxf(g.w, 0.f);

            float4 Pi4 = __ldg((const float4*)&g_Pi[(size_t)src * HH + col]);
            float4 Pj4 = __ldg((const float4*)&g_Pj[(size_t)tgt * HH + col]);
            float4 ea4 = *(const float4*)&sEA[row * HH + col];

            float4 pre;
            pre.x = fmaf(g.x, sigmoidf_(Pi4.x + Pj4.x + bs.x), ea4.x);
            pre.y = fmaf(g.y, sigmoidf_(Pi4.y + Pj4.y + bs.y), ea4.y);
            pre.z = fmaf(g.z, sigmoidf_(Pi4.z + Pj4.z + bs.z), ea4.z);
            pre.w = fmaf(g.w, sigmoidf_(Pi4.w + Pj4.w + bs.w), ea4.w);

            float ssum = pre.x + pre.y + pre.z + pre.w;
#pragma unroll
            for (int off = 16; off >= 1; off >>= 1)
                ssum += __shfl_xor_sync(0xffffffffu, ssum, off);
            float mu = ssum * (1.0f / 128.0f);
            float4 dv;
            dv.x = pre.x - mu; dv.y = pre.y - mu;
            dv.z = pre.z - mu; dv.w = pre.w - mu;
            float sq = dv.x * dv.x + dv.y * dv.y + dv.z * dv.z + dv.w * dv.w;
#pragma unroll
            for (int off = 16; off >= 1; off >>= 1)
                sq += __shfl_xor_sync(0xffffffffu, sq, off);
            float rstd = rsqrtf(sq * (1.0f / 128.0f) + 1e-5f);

            float4 h4;
            h4.x = fmaf(dv.x * rstd, gm.x, bt.x);
            h4.y = fmaf(dv.y * rstd, gm.y, bt.y);
            h4.z = fmaf(dv.z * rstd, gm.z, bt.z);
            h4.w = fmaf(dv.w * rstd, gm.w, bt.w);

            size_t o = (size_t)e * HH + col;
            __half2 hh0 = __float22half2_rn(make_float2(h4.x, h4.y));
            __half2 hh1 = __float22half2_rn(make_float2(h4.z, h4.w));
            *(uint2*)&g_H16[o] = make_uint2(h2u(hh0), h2u(hh1));

            __half2 ee0 = __float22half2_rn(make_float2(ea4.x, ea4.y));
            __half2 ee1 = __float22half2_rn(make_float2(ea4.z, ea4.w));
            *(uint2*)&g_EA16[o] = make_uint2(h2u(ee0), h2u(ee1));
        }
        CP_WAIT(0);
        __syncthreads();
        cur ^= 1;
    }
}

// ---------------------------------------------------------------------------
// GEMM v2: 256 threads, occ 2 (32 warps/SM), 64-row tiles, single-buffered.
// gate = h @ Wgate, res = ea @ Wres via fp16 m16n8k16 mma; fused epilogue.
// ---------------------------------------------------------------------------
__global__ __launch_bounds__(256, 2) void gemm_kernel(
    const float* __restrict__ Wgate, const float* __restrict__ Wres,
    float* __restrict__ out) {
    extern __shared__ char smc[];
    __half* sWg = (__half*)(smc + GOFF_WG);
    __half* sWr = (__half*)(smc + GOFF_WR);
    __half* sH  = (__half*)(smc + GOFF_H);
    __half* sE  = (__half*)(smc + GOFF_E);
    uint32_t sb = smem_u32(smc);

    int tid = threadIdx.x;
    int lane = tid & 31;
    int w = tid >> 5;
    int gid = lane >> 2;
    int tig = lane & 3;
    int mb = (w >> 2) * 32;   // 0 or 32
    int nb = (w & 3) * 32;

    // stage weights once: sW[n][k] (transposed), stride 136 halves
    for (int i = tid; i < 16384; i += 256) {
        int n = i & 127, k = i >> 7;
        sWg[n * 136 + k] = __float2half(Wgate[k * HH + n]);
        sWr[n * 136 + k] = __float2half(Wres[k * HH + n]);
    }
    __syncthreads();

    for (int t = blockIdx.x; t < NT2; t += GGRID) {
        long base = (long)t * 64;

        // load 64-row tiles via cp.async (latency covered by co-resident CTA)
        for (int c = tid; c < 1024; c += 256) {
            int r = c >> 4, q = c & 15;
            CP_ASYNC_16(sb + GOFF_H + r * 272 + q * 16,
                        (const void*)(g_H16 + (base + r) * HH + q * 8));
            CP_ASYNC_16(sb + GOFF_E + r * 272 + q * 16,
                        (const void*)(g_EA16 + (base + r) * HH + q * 8));
        }
        CP_COMMIT();
        CP_WAIT(0);
        __syncthreads();

        float aG[2][4][4];
        float aR[2][4][4];
#pragma unroll
        for (int mt = 0; mt < 2; mt++)
#pragma unroll
            for (int nt = 0; nt < 4; nt++)
#pragma unroll
                for (int q = 0; q < 4; q++) { aG[mt][nt][q] = 0.f; aR[mt][nt][q] = 0.f; }

#pragma unroll
        for (int kt = 0; kt < 8; kt++) {
            int k0 = kt * 16;
            uint32_t bg[4][2], br[4][2];
#pragma unroll
            for (int nt = 0; nt < 4; nt++) {
                int n = nb + nt * 8 + gid;
                bg[nt][0] = *(const uint32_t*)&sWg[n * 136 + k0 + 2 * tig];
                bg[nt][1] = *(const uint32_t*)&sWg[n * 136 + k0 + 2 * tig + 8];
                br[nt][0] = *(const uint32_t*)&sWr[n * 136 + k0 + 2 * tig];
                br[nt][1] = *(const uint32_t*)&sWr[n * 136 + k0 + 2 * tig + 8];
            }
#pragma unroll
            for (int mt = 0; mt < 2; mt++) {
                int r0 = mb + mt * 16 + gid;
                uint32_t ha0 = *(const uint32_t*)&sH[r0 * 136 + k0 + 2 * tig];
                uint32_t ha1 = *(const uint32_t*)&sH[(r0 + 8) * 136 + k0 + 2 * tig];
                uint32_t ha2 = *(const uint32_t*)&sH[r0 * 136 + k0 + 2 * tig + 8];
                uint32_t ha3 = *(const uint32_t*)&sH[(r0 + 8) * 136 + k0 + 2 * tig + 8];
                uint32_t ea0 = *(const uint32_t*)&sE[r0 * 136 + k0 + 2 * tig];
                uint32_t ea1 = *(const uint32_t*)&sE[(r0 + 8) * 136 + k0 + 2 * tig];
                uint32_t ea2 = *(const uint32_t*)&sE[r0 * 136 + k0 + 2 * tig + 8];
                uint32_t ea3 = *(const uint32_t*)&sE[(r0 + 8) * 136 + k0 + 2 * tig + 8];
#pragma unroll
                for (int nt = 0; nt < 4; nt++) {
                    mma_f16(aG[mt][nt], ha0, ha1, ha2, ha3, bg[nt][0], bg[nt][1]);
                    mma_f16(aR[mt][nt], ea0, ea1, ea2, ea3, br[nt][0], br[nt][1]);
                }
            }
        }

        // epilogue: out = h + sigmoid(gate) * (res - h), h from smem fp16 tile
#pragma unroll
        for (int mt = 0; mt < 2; mt++) {
#pragma unroll
            for (int nt = 0; nt < 4; nt++) {
                int c0 = nb + nt * 8 + 2 * tig;
#pragma unroll
                for (int hf = 0; hf < 2; hf++) {
                    int r = mb + mt * 16 + gid + hf * 8;
                    long e = base + r;
                    float2 h2 = __half22float2(*(const __half2*)&sH[r * 136 + c0]);
                    float s0 = sigmoidf_(aG[mt][nt][hf * 2 + 0]);
                    float s1 = sigmoidf_(aG[mt][nt][hf * 2 + 1]);
                    float2 o;
                    o.x = fmaf(s0, aR[mt][nt][hf * 2 + 0] - h2.x, h2.x);
                    o.y = fmaf(s1, aR[mt][nt][hf * 2 + 1] - h2.y, h2.y);
                    *(float2*)&out[(size_t)e * HH + c0] = o;
                }
            }
        }
        __syncthreads();   // tile consumed before next load overwrites
    }
}

// ---------------------------------------------------------------------------
extern "C" void kernel_launch(void* const* d_in, const int* in_sizes, int n_in,
                              void* d_out, int out_size) {
    const float* pos_i     = (const float*)d_in[0];
    const float* pos_j     = (const float*)d_in[1];
    const float* hd_i      = (const float*)d_in[2];
    const float* hd_j      = (const float*)d_in[3];
    const int*   eidx      = (const int*)d_in[4];
    const float* edge_attr = (const float*)d_in[5];
    const float* embs_i    = (const float*)d_in[6];
    const float* embs_j    = (const float*)d_in[7];
    const float* Wgeo      = (const float*)d_in[8];
    const float* Wpair     = (const float*)d_in[9];
    const float* Wsem      = (const float*)d_in[10];
    const float* bsem      = (const float*)d_in[11];
    const float* gamma     = (const float*)d_in[12];
    const float* beta      = (const float*)d_in[13];
    const float* Wgate     = (const float*)d_in[14];
    const float* Wres      = (const float*)d_in[15];

    const int smem_pk = (128 * SP * 2 + 64 * SP * 2) * 4;  // 202752

    cudaFuncSetAttribute(pk_kernel, cudaFuncAttributeMaxDynamicSharedMemorySize,
                         smem_pk);
    cudaFuncSetAttribute(phaseA_kernel, cudaFuncAttributeMaxDynamicSharedMemorySize,
                         ASMEM);
    cudaFuncSetAttribute(gemm_kernel, cudaFuncAttributeMaxDynamicSharedMemorySize,
                         GSMEM);

    pk_kernel<<<148, 256, smem_pk>>>(embs_i, embs_j, Wsem, Wgeo, Wpair);
    phaseA_kernel<<<PGRID, 512, ASMEM>>>(pos_i, pos_j, hd_i, hd_j, eidx,
                                         edge_attr, bsem, gamma, beta);
    gemm_kernel<<<GGRID, 256, GSMEM>>>(Wgate, Wres, (float*)d_out);
}

// round 15
// speedup vs baseline: 1.2702x; 1.0345x over previous
#include <cuda_runtime.h>
#include <cuda_fp16.h>
#include <cstdint>
#include <cstring>
#include <math.h>

#define NN 50000
#define EE 600000
#define HH 128
#define SP 132          // pk kernel padded stride (floats)
#define NPT 782         // ceil(NN/64) node tiles
#define NT2 9375        // EE/64 tiles (phaseA + gemm)
#define PGRID 296
#define GGRID 296

// ---- phaseA smem byte offsets (dynamic) ----
#define AOFF_WC   0          // 10*128 floats = 5120
#define AOFF_IDX0 5120
#define AOFF_IDX1 5632
#define AOFF_EA0  6144       // 64*128 floats = 32768
#define AOFF_EA1  38912
#define ASMEM     71680

// ---- gemm smem byte offsets (dynamic) ----
#define GOFF_WG   0          // 128*136 half = 34816
#define GOFF_WR   34816
#define GOFF_H    69632      // 64*136 half = 17408
#define GOFF_E    87040
#define GSMEM     104448

// Scratch (__device__ globals: alloc-free rule)
__device__ __align__(16) __half g_Pi[NN * HH];   // fp16 node tables
__device__ __align__(16) __half g_Pj[NN * HH];
__device__ __align__(16) float  g_Wcomb[10 * HH];
__device__ __align__(16) __half g_H16[(size_t)EE * HH];
__device__ __align__(16) __half g_EA16[(size_t)EE * HH];

__device__ __forceinline__ float sigmoidf_(float x) {
    return 1.0f / (1.0f + __expf(-x));
}
__device__ __forceinline__ uint32_t h2u(__half2 v) {
    uint32_t r;
    memcpy(&r, &v, 4);
    return r;
}
__device__ __forceinline__ __half2 u2h(uint32_t v) {
    __half2 h;
    memcpy(&h, &v, 4);
    return h;
}
__device__ __forceinline__ unsigned f2tf32(float x) {
    unsigned r;
    asm("cvt.rna.tf32.f32 %0, %1;" : "=r"(r) : "f"(x));
    return r;
}
__device__ __forceinline__ uint32_t smem_u32(const void* smem_ptr) {
    uint32_t addr;
    asm("{ .reg .u64 tmp; cvta.to.shared.u64 tmp, %1; cvt.u32.u64 %0, tmp; }"
        : "=r"(addr) : "l"(smem_ptr));
    return addr;
}
__device__ __forceinline__ void mma_tf32(float* d, unsigned a0, unsigned a1,
                                         unsigned a2, unsigned a3,
                                         unsigned b0, unsigned b1) {
    asm volatile(
        "mma.sync.aligned.m16n8k8.row.col.f32.tf32.tf32.f32 "
        "{%0,%1,%2,%3}, {%4,%5,%6,%7}, {%8,%9}, {%0,%1,%2,%3};\n"
        : "+f"(d[0]), "+f"(d[1]), "+f"(d[2]), "+f"(d[3])
        : "r"(a0), "r"(a1), "r"(a2), "r"(a3), "r"(b0), "r"(b1));
}
__device__ __forceinline__ void mma_f16(float* d, uint32_t a0, uint32_t a1,
                                        uint32_t a2, uint32_t a3,
                                        uint32_t b0, uint32_t b1) {
    asm volatile(
        "mma.sync.aligned.m16n8k16.row.col.f32.f16.f16.f32 "
        "{%0,%1,%2,%3}, {%4,%5,%6,%7}, {%8,%9}, {%0,%1,%2,%3};\n"
        : "+f"(d[0]), "+f"(d[1]), "+f"(d[2]), "+f"(d[3])
        : "r"(a0), "r"(a1), "r"(a2), "r"(a3), "r"(b0), "r"(b1));
}

#define LDSM_X4(r0, r1, r2, r3, addr) \
    asm volatile( \
        "ldmatrix.sync.aligned.m8n8.x4.shared.b16 {%0,%1,%2,%3}, [%4];" \
        : "=r"(r0), "=r"(r1), "=r"(r2), "=r"(r3) : "r"(addr))

#define CP_ASYNC_16(dst_u32, src_ptr) \
    asm volatile("cp.async.cg.shared.global [%0], [%1], 16;" \
                 :: "r"(dst_u32), "l"(src_ptr) : "memory")
#define CP_COMMIT() asm volatile("cp.async.commit_group;" ::: "memory")
#define CP_WAIT(n)  asm volatile("cp.async.wait_group %0;" :: "n"(n) : "memory")

// ---------------------------------------------------------------------------
// Setup kernel: wcomb (blocks 0-9) + P precompute (tf32 mma), fp16 output.
// ---------------------------------------------------------------------------
__global__ __launch_bounds__(256, 1) void pk_kernel(const float* __restrict__ Ei,
                                                    const float* __restrict__ Ej,
                                                    const float* __restrict__ Wsem,
                                                    const float* __restrict__ Wgeo,
                                                    const float* __restrict__ Wpair) {
    extern __shared__ float sm[];
    float* sWt = sm;
    float* sWb = sWt + 128 * SP;
    float* sAi = sWb + 128 * SP;
    float* sAj = sAi + 64 * SP;

    int tid = threadIdx.x;
    int lane = tid & 31;
    int w = tid >> 5;

    if (blockIdx.x < 10 && tid < 128) {
        int c = tid;
        int d = blockIdx.x;
        int dd = d % 5;
        const float* wp = Wpair + (d / 5) * 128 * HH;
        float acc = 0.0f;
#pragma unroll 16
        for (int m = 0; m < 128; m++)
            acc = fmaf(Wgeo[dd * HH + m], wp[m * HH + c], acc);
        g_Wcomb[d * HH + c] = acc;
    }

    for (int i = tid; i < 4096; i += 256) {
        int k = i >> 5, c4 = i & 31;
        float4 t = ((const float4*)Wsem)[i];
        float4 b = ((const float4*)(Wsem + 128 * HH))[i];
        *(uint4*)&sWt[k * SP + c4 * 4] =
            make_uint4(f2tf32(t.x), f2tf32(t.y), f2tf32(t.z), f2tf32(t.w));
        *(uint4*)&sWb[k * SP + c4 * 4] =
            make_uint4(f2tf32(b.x), f2tf32(b.y), f2tf32(b.z), f2tf32(b.w));
    }

    const float* A = (w < 4) ? sAi : sAj;
    const float* W = (w < 4) ? sWt : sWb;
    int nb = (w & 3) * 32;
    int gid = lane >> 2, tig = lane & 3;

    for (int t = blockIdx.x; t < NPT; t += (int)gridDim.x) {
        int base = t * 64;
        __syncthreads();
        for (int i = tid; i < 2048; i += 256) {
            int r = i >> 5, c4 = i & 31;
            int row = base + r;
            float4 v = make_float4(0.f, 0.f, 0.f, 0.f);
            float4 u = make_float4(0.f, 0.f, 0.f, 0.f);
            if (row < NN) {
                v = ((const float4*)Ei)[row * 32 + c4];
                u = ((const float4*)Ej)[row * 32 + c4];
            }
            *(uint4*)&sAi[r * SP + c4 * 4] =
                make_uint4(f2tf32(v.x), f2tf32(v.y), f2tf32(v.z), f2tf32(v.w));
            *(uint4*)&sAj[r * SP + c4 * 4] =
                make_uint4(f2tf32(u.x), f2tf32(u.y), f2tf32(u.z), f2tf32(u.w));
        }
        __syncthreads();

        float acc[4][4][4];
#pragma unroll
        for (int mt = 0; mt < 4; mt++)
#pragma unroll
            for (int nt = 0; nt < 4; nt++)
#pragma unroll
                for (int q = 0; q < 4; q++) { acc[mt][nt][q] = 0.f; }

#pragma unroll
        for (int kt = 0; kt < 16; kt++) {
            int k0 = kt * 8;
            unsigned b[4][2];
#pragma unroll
            for (int nt = 0; nt < 4; nt++) {
                int n = nb + nt * 8 + gid;
                b[nt][0] = __float_as_uint(W[(k0 + tig) * SP + n]);
                b[nt][1] = __float_as_uint(W[(k0 + 4 + tig) * SP + n]);
            }
#pragma unroll
            for (int mt = 0; mt < 4; mt++) {
                int m = mt * 16;
                unsigned a0 = __float_as_uint(A[(m + gid) * SP + k0 + tig]);
                unsigned a1 = __float_as_uint(A[(m + gid + 8) * SP + k0 + tig]);
                unsigned a2 = __float_as_uint(A[(m + gid) * SP + k0 + tig + 4]);
                unsigned a3 = __float_as_uint(A[(m + gid + 8) * SP + k0 + tig + 4]);
#pragma unroll
                for (int nt = 0; nt < 4; nt++)
                    mma_tf32(acc[mt][nt], a0, a1, a2, a3, b[nt][0], b[nt][1]);
            }
        }

        __half* G = (w < 4) ? g_Pi : g_Pj;
#pragma unroll
        for (int mt = 0; mt < 4; mt++)
#pragma unroll
            for (int nt = 0; nt < 4; nt++) {
                int row0 = base + mt * 16 + gid;
                int col = nb + nt * 8 + 2 * tig;
                if (row0 < NN)
                    *(__half2*)&G[(size_t)row0 * HH + col] =
                        __float22half2_rn(make_float2(acc[mt][nt][0], acc[mt][nt][1]));
                int row1 = row0 + 8;
                if (row1 < NN)
                    *(__half2*)&G[(size_t)row1 * HH + col] =
                        __float22half2_rn(make_float2(acc[mt][nt][2], acc[mt][nt][3]));
            }
    }
}

// ---------------------------------------------------------------------------
// Phase A: persistent 296 CTAs x 512 thr (occ 2), cp.async double-buffered
// eidx + edge_attr; fp16 Pi/Pj gathers (half the bytes of fp32).
// ---------------------------------------------------------------------------
__global__ __launch_bounds__(512, 2) void phaseA_kernel(
    const float* __restrict__ pos_i, const float* __restrict__ pos_j,
    const float* __restrict__ hd_i, const float* __restrict__ hd_j,
    const int* __restrict__ eidx, const float* __restrict__ edge_attr,
    const float* __restrict__ b_sem, const float* __restrict__ gamma,
    const float* __restrict__ beta) {
    extern __shared__ char smc[];
    float* sWc = (float*)(smc + AOFF_WC);
    uint32_t sb = smem_u32(smc);

    int tid = threadIdx.x;
    int lane = tid & 31;
    int w = tid >> 5;
    int col = lane * 4;

    for (int i = tid; i < 1280; i += 512) sWc[i] = g_Wcomb[i];

    float4 bs = *(const float4*)&b_sem[col];
    float4 gm = *(const float4*)&gamma[col];
    float4 bt = *(const float4*)&beta[col];

    const uint32_t idxOff[2] = {AOFF_IDX0, AOFF_IDX1};
    const uint32_t eaOff[2] = {AOFF_EA0, AOFF_EA1};

    {
        long base = (long)blockIdx.x * 64;
        if (tid < 32) {
            const int* srcp = (tid < 16) ? (eidx + base + (tid & 15) * 4)
                                         : (eidx + EE + base + (tid & 15) * 4);
            CP_ASYNC_16(sb + AOFF_IDX0 + ((tid < 16) ? 0 : 256) + (tid & 15) * 16,
                        srcp);
        }
        for (int c = tid; c < 2048; c += 512) {
            int r = c >> 5, q = c & 31;
            CP_ASYNC_16(sb + AOFF_EA0 + r * 512 + q * 16,
                        edge_attr + (base + r) * HH + q * 4);
        }
        CP_COMMIT();
    }
    CP_WAIT(0);
    __syncthreads();

    int cur = 0;
    for (int t = blockIdx.x; t < NT2; t += PGRID) {
        long base = (long)t * 64;
        const int* sIdx = (const int*)(smc + idxOff[cur]);
        const float* sEA = (const float*)(smc + eaOff[cur]);

        int nt2 = t + PGRID;
        if (nt2 < NT2) {
            long nbase = (long)nt2 * 64;
            if (tid < 32) {
                const int* srcp = (tid < 16) ? (eidx + nbase + (tid & 15) * 4)
                                             : (eidx + EE + nbase + (tid & 15) * 4);
                CP_ASYNC_16(sb + idxOff[cur ^ 1] + ((tid < 16) ? 0 : 256) +
                                (tid & 15) * 16,
                            srcp);
            }
            for (int c = tid; c < 2048; c += 512) {
                int r = c >> 5, q = c & 31;
                CP_ASYNC_16(sb + eaOff[cur ^ 1] + r * 512 + q * 16,
                            edge_attr + (nbase + r) * HH + q * 4);
            }
            CP_COMMIT();
        }

#pragma unroll 2
        for (int it = 0; it < 4; it++) {
            int row = w + 16 * it;
            long e = base + row;
            int src = sIdx[row];
            int tgt = sIdx[64 + row];

            float2 pvi = __ldg(&((const float2*)pos_i)[src]);
            float2 pvj = __ldg(&((const float2*)pos_j)[tgt]);
            float ang_i = __ldg(&hd_i[src]);
            float ang_j = __ldg(&hd_j[tgt]);
            float dx = pvi.x - pvj.x;
            float dy = pvi.y - pvj.y;

            float sj, cj;
            __sincosf(ang_j, &sj, &cj);
            float x1 = dx * cj + dy * sj;
            float y1 = -dx * sj + dy * cj;
            float len1 = sqrtf(x1 * x1 + y1 * y1);
            float il1 = (len1 > 0.f) ? (1.f / len1) : 0.f;
            float ct1 = (len1 > 0.f) ? (x1 * il1) : 1.f;
            float st1 = y1 * il1;

            float si, ci;
            __sincosf(ang_i, &si, &ci);
            float x2 = -dx * ci - dy * si;
            float y2 = dx * si - dy * ci;
            float len2 = sqrtf(x2 * x2 + y2 * y2);
            float il2 = (len2 > 0.f) ? (1.f / len2) : 0.f;
            float ct2 = (len2 > 0.f) ? (x2 * il2) : 1.f;
            float st2 = y2 * il2;

            float shd, chd;
            __sincosf(ang_i - ang_j, &shd, &chd);

            float raw[10];
            raw[0] = len1; raw[1] = ct1; raw[2] = st1; raw[3] = chd; raw[4] = shd;
            raw[5] = len2; raw[6] = ct2; raw[7] = st2; raw[8] = chd; raw[9] = -shd;

            float4 g = make_float4(0.f, 0.f, 0.f, 0.f);
#pragma unroll
            for (int d = 0; d < 10; d++) {
                float4 wc = *(const float4*)&sWc[d * HH + col];
                g.x = fmaf(raw[d], wc.x, g.x);
                g.y = fmaf(raw[d], wc.y, g.y);
                g.z = fmaf(raw[d], wc.z, g.z);
                g.w = fmaf(raw[d], wc.w, g.w);
            }
            g.x = fmaxf(g.x, 0.f); g.y = fmaxf(g.y, 0.f);
            g.z = fmaxf(g.z, 0.f); g.w = fmaxf(g.w, 0.f);

            uint2 piu = __ldg((const uint2*)&g_Pi[(size_t)src * HH + col]);
            uint2 pju = __ldg((const uint2*)&g_Pj[(size_t)tgt * HH + col]);
            float2 pi01 = __half22float2(u2h(piu.x));
            float2 pi23 = __half22float2(u2h(piu.y));
            float2 pj01 = __half22float2(u2h(pju.x));
            float2 pj23 = __half22float2(u2h(pju.y));
            float4 ea4 = *(const float4*)&sEA[row * HH + col];

            float4 pre;
            pre.x = fmaf(g.x, sigmoidf_(pi01.x + pj01.x + bs.x), ea4.x);
            pre.y = fmaf(g.y, sigmoidf_(pi01.y + pj01.y + bs.y), ea4.y);
            pre.z = fmaf(g.z, sigmoidf_(pi23.x + pj23.x + bs.z), ea4.z);
            pre.w = fmaf(g.w, sigmoidf_(pi23.y + pj23.y + bs.w), ea4.w);

            float ssum = pre.x + pre.y + pre.z + pre.w;
#pragma unroll
            for (int off = 16; off >= 1; off >>= 1)
                ssum += __shfl_xor_sync(0xffffffffu, ssum, off);
            float mu = ssum * (1.0f / 128.0f);
            float4 dv;
            dv.x = pre.x - mu; dv.y = pre.y - mu;
            dv.z = pre.z - mu; dv.w = pre.w - mu;
            float sq = dv.x * dv.x + dv.y * dv.y + dv.z * dv.z + dv.w * dv.w;
#pragma unroll
            for (int off = 16; off >= 1; off >>= 1)
                sq += __shfl_xor_sync(0xffffffffu, sq, off);
            float rstd = rsqrtf(sq * (1.0f / 128.0f) + 1e-5f);

            float4 h4;
            h4.x = fmaf(dv.x * rstd, gm.x, bt.x);
            h4.y = fmaf(dv.y * rstd, gm.y, bt.y);
            h4.z = fmaf(dv.z * rstd, gm.z, bt.z);
            h4.w = fmaf(dv.w * rstd, gm.w, bt.w);

            size_t o = (size_t)e * HH + col;
            __half2 hh0 = __float22half2_rn(make_float2(h4.x, h4.y));
            __half2 hh1 = __float22half2_rn(make_float2(h4.z, h4.w));
            *(uint2*)&g_H16[o] = make_uint2(h2u(hh0), h2u(hh1));

            __half2 ee0 = __float22half2_rn(make_float2(ea4.x, ea4.y));
            __half2 ee1 = __float22half2_rn(make_float2(ea4.z, ea4.w));
            *(uint2*)&g_EA16[o] = make_uint2(h2u(ee0), h2u(ee1));
        }
        CP_WAIT(0);
        __syncthreads();
        cur ^= 1;
    }
}

// ---------------------------------------------------------------------------
// GEMM: 256 threads, occ 2, 64-row tiles; fragments loaded via ldmatrix.x4.
// ---------------------------------------------------------------------------
__global__ __launch_bounds__(256, 2) void gemm_kernel(
    const float* __restrict__ Wgate, const float* __restrict__ Wres,
    float* __restrict__ out) {
    extern __shared__ char smc[];
    __half* sWg = (__half*)(smc + GOFF_WG);
    __half* sWr = (__half*)(smc + GOFF_WR);
    __half* sH  = (__half*)(smc + GOFF_H);
    __half* sE  = (__half*)(smc + GOFF_E);
    uint32_t sb = smem_u32(smc);

    int tid = threadIdx.x;
    int lane = tid & 31;
    int w = tid >> 5;
    int gid = lane >> 2;
    int tig = lane & 3;
    int mb = (w >> 2) * 32;   // 0 or 32
    int nb = (w & 3) * 32;

    // stage weights once: sW[n][k] (transposed), stride 136 halves
    for (int i = tid; i < 16384; i += 256) {
        int n = i & 127, k = i >> 7;
        sWg[n * 136 + k] = __float2half(Wgate[k * HH + n]);
        sWr[n * 136 + k] = __float2half(Wres[k * HH + n]);
    }
    __syncthreads();

    // per-lane ldmatrix address offsets (bytes), stride 272 B per row
    int rowIn = lane & 7;
    uint32_t aOff = (uint32_t)((rowIn + ((lane >> 3) & 1) * 8) * 272 +
                               ((lane >> 4) * 8) * 2);
    uint32_t bOff = (uint32_t)((rowIn + (lane >> 4) * 8) * 272 +
                               (((lane >> 3) & 1) * 8) * 2);

    uint32_t wgB0 = sb + GOFF_WG + (uint32_t)nb * 272 + bOff;
    uint32_t wgB1 = wgB0 + 16 * 272;
    uint32_t wrB0 = sb + GOFF_WR + (uint32_t)nb * 272 + bOff;
    uint32_t wrB1 = wrB0 + 16 * 272;
    uint32_t hA0 = sb + GOFF_H + (uint32_t)mb * 272 + aOff;
    uint32_t hA1 = hA0 + 16 * 272;
    uint32_t eA0 = sb + GOFF_E + (uint32_t)mb * 272 + aOff;
    uint32_t eA1 = eA0 + 16 * 272;

    for (int t = blockIdx.x; t < NT2; t += GGRID) {
        long base = (long)t * 64;

        for (int c = tid; c < 1024; c += 256) {
            int r = c >> 4, q = c & 15;
            CP_ASYNC_16(sb + GOFF_H + r * 272 + q * 16,
                        (const void*)(g_H16 + (base + r) * HH + q * 8));
            CP_ASYNC_16(sb + GOFF_E + r * 272 + q * 16,
                        (const void*)(g_EA16 + (base + r) * HH + q * 8));
        }
        CP_COMMIT();
        CP_WAIT(0);
        __syncthreads();

        float aG[2][4][4];
        float aR[2][4][4];
#pragma unroll
        for (int mt = 0; mt < 2; mt++)
#pragma unroll
            for (int nt = 0; nt < 4; nt++)
#pragma unroll
                for (int q = 0; q < 4; q++) { aG[mt][nt][q] = 0.f; aR[mt][nt][q] = 0.f; }

#pragma unroll
        for (int kt = 0; kt < 8; kt++) {
            uint32_t kB = (uint32_t)(kt * 32);   // 16 halves = 32 bytes
            uint32_t bg[4][2], br[4][2];
            LDSM_X4(bg[0][0], bg[0][1], bg[1][0], bg[1][1], wgB0 + kB);
            LDSM_X4(bg[2][0], bg[2][1], bg[3][0], bg[3][1], wgB1 + kB);
            LDSM_X4(br[0][0], br[0][1], br[1][0], br[1][1], wrB0 + kB);
            LDSM_X4(br[2][0], br[2][1], br[3][0], br[3][1], wrB1 + kB);
#pragma unroll
            for (int mt = 0; mt < 2; mt++) {
                uint32_t ha0, ha1, ha2, ha3, ea0, ea1, ea2, ea3;
                LDSM_X4(ha0, ha1, ha2, ha3, (mt ? hA1 : hA0) + kB);
                LDSM_X4(ea0, ea1, ea2, ea3, (mt ? eA1 : eA0) + kB);
#pragma unroll
                for (int nt = 0; nt < 4; nt++) {
                    mma_f16(aG[mt][nt], ha0, ha1, ha2, ha3, bg[nt][0], bg[nt][1]);
                    mma_f16(aR[mt][nt], ea0, ea1, ea2, ea3, br[nt][0], br[nt][1]);
                }
            }
        }

        // epilogue: out = h + sigmoid(gate) * (res - h), h from smem fp16 tile
#pragma unroll
        for (int mt = 0; mt < 2; mt++) {
#pragma unroll
            for (int nt = 0; nt < 4; nt++) {
                int c0 = nb + nt * 8 + 2 * tig;
#pragma unroll
                for (int hf = 0; hf < 2; hf++) {
                    int r = mb + mt * 16 + gid + hf * 8;
                    long e = base + r;
                    float2 h2 = __half22float2(*(const __half2*)&sH[r * 136 + c0]);
                    float s0 = sigmoidf_(aG[mt][nt][hf * 2 + 0]);
                    float s1 = sigmoidf_(aG[mt][nt][hf * 2 + 1]);
                    float2 o;
                    o.x = fmaf(s0, aR[mt][nt][hf * 2 + 0] - h2.x, h2.x);
                    o.y = fmaf(s1, aR[mt][nt][hf * 2 + 1] - h2.y, h2.y);
                    *(float2*)&out[(size_t)e * HH + c0] = o;
                }
            }
        }
        __syncthreads();
    }
}

// ---------------------------------------------------------------------------
extern "C" void kernel_launch(void* const* d_in, const int* in_sizes, int n_in,
                              void* d_out, int out_size) {
    const float* pos_i     = (const float*)d_in[0];
    const float* pos_j     = (const float*)d_in[1];
    const float* hd_i      = (const float*)d_in[2];
    const float* hd_j      = (const float*)d_in[3];
    const int*   eidx      = (const int*)d_in[4];
    const float* edge_attr = (const float*)d_in[5];
    const float* embs_i    = (const float*)d_in[6];
    const float* embs_j    = (const float*)d_in[7];
    const float* Wgeo      = (const float*)d_in[8];
    const float* Wpair     = (const float*)d_in[9];
    const float* Wsem      = (const float*)d_in[10];
    const float* bsem      = (const float*)d_in[11];
    const float* gamma     = (const float*)d_in[12];
    const float* beta      = (const float*)d_in[13];
    const float* Wgate     = (const float*)d_in[14];
    const float* Wres      = (const float*)d_in[15];

    const int smem_pk = (128 * SP * 2 + 64 * SP * 2) * 4;  // 202752

    cudaFuncSetAttribute(pk_kernel, cudaFuncAttributeMaxDynamicSharedMemorySize,
                         smem_pk);
    cudaFuncSetAttribute(phaseA_kernel, cudaFuncAttributeMaxDynamicSharedMemorySize,
                         ASMEM);
    cudaFuncSetAttribute(gemm_kernel, cudaFuncAttributeMaxDynamicSharedMemorySize,
                         GSMEM);

    pk_kernel<<<148, 256, smem_pk>>>(embs_i, embs_j, Wsem, Wgeo, Wpair);
    phaseA_kernel<<<PGRID, 512, ASMEM>>>(pos_i, pos_j, hd_i, hd_j, eidx,
                                         edge_attr, bsem, gamma, beta);
    gemm_kernel<<<GGRID, 256, GSMEM>>>(Wgate, Wres, (float*)d_out);
}